// round 5
// baseline (speedup 1.0000x reference)
#include <cuda_runtime.h>
#include <cstdint>

#define B_  4
#define T_  2048
#define C_  1024
#define NH_ 16
#define HS_ 64
#define M_  (B_*T_)   // 8192

// ---------------- scratch (static device arrays: allocation-free) ----------
__device__ float g_q [(size_t)M_ * C_];   // [B,H,T,HS] tf32-rounded
__device__ float g_k [(size_t)M_ * C_];
__device__ float g_v [(size_t)M_ * C_];
__device__ float g_y [(size_t)M_ * C_];   // [B,T,C]   tf32-rounded
__device__ float g_xt[(size_t)M_ * C_];   // x rounded to tf32
__device__ float g_wt[(size_t)4 * C_ * C_]; // W^T (K-major, tf32): q,k,v,p

// ---------------- helpers ---------------------------------------------------
__device__ __forceinline__ float rn_tf32(float x) {
    uint32_t u;
    asm("cvt.rna.tf32.f32 %0, %1;" : "=r"(u) : "f"(x));
    return __uint_as_float(u);
}
__device__ __forceinline__ uint32_t fbits(float f) { return __float_as_uint(f); }
__device__ __forceinline__ float ex2(float x) {
    float y; asm("ex2.approx.f32 %0, %1;" : "=f"(y) : "f"(x)); return y;
}
__device__ __forceinline__ void mma_tf32(float* d, const uint32_t* a, const uint32_t* b) {
    asm volatile("mma.sync.aligned.m16n8k8.row.col.f32.tf32.tf32.f32 "
                 "{%0,%1,%2,%3}, {%4,%5,%6,%7}, {%8,%9}, {%0,%1,%2,%3};"
                 : "+f"(d[0]), "+f"(d[1]), "+f"(d[2]), "+f"(d[3])
                 : "r"(a[0]), "r"(a[1]), "r"(a[2]), "r"(a[3]), "r"(b[0]), "r"(b[1]));
}

// ---------------- prepass: round x to tf32 ---------------------------------
__global__ __launch_bounds__(256) void round_x_kernel(const float* __restrict__ x) {
    size_t i0 = ((size_t)blockIdx.x * 256 + threadIdx.x) * 4;
    const size_t stride = (size_t)gridDim.x * 256 * 4;
    for (int r = 0; r < 4; r++) {
        float4 v = *(const float4*)(x + i0);
        v.x = rn_tf32(v.x); v.y = rn_tf32(v.y); v.z = rn_tf32(v.z); v.w = rn_tf32(v.w);
        *(float4*)(g_xt + i0) = v;
        i0 += stride;
    }
}

// ---------------- prepass: transpose + round W -> g_wt[slot][n][k] ---------
__global__ __launch_bounds__(256) void transpose_w_kernel(const float* __restrict__ Wq,
                                                          const float* __restrict__ Wk,
                                                          const float* __restrict__ Wv,
                                                          const float* __restrict__ Wp) {
    __shared__ float tile[32][33];
    const int z = blockIdx.z;
    const float* src = (z == 0) ? Wq : (z == 1) ? Wk : (z == 2) ? Wv : Wp;
    float* dst = g_wt + ((size_t)z << 20);
    int x = blockIdx.x * 32 + threadIdx.x;   // n
    int y = blockIdx.y * 32 + threadIdx.y;   // k
    #pragma unroll
    for (int i = 0; i < 32; i += 8)
        tile[threadIdx.y + i][threadIdx.x] = src[(size_t)(y + i) * C_ + x];
    __syncthreads();
    int xo = blockIdx.y * 32 + threadIdx.x;  // k
    int yo = blockIdx.x * 32 + threadIdx.y;  // n
    #pragma unroll
    for (int i = 0; i < 32; i += 8)
        dst[(size_t)(yo + i) * C_ + xo] = rn_tf32(tile[threadIdx.x][threadIdx.y + i]);
}

// ---------------- tf32 mma.sync GEMM ----------------------------------------
// out[m,n] = sum_k A[m,k] * Bt[n,k]; 128x128x16 tiles, 256 thr, 64x32 warp tile
#define GBM 128
#define GBN 128
#define GBK 16
#define GPAD 20
#define NCH  (C_ / GBK)   // 64

__device__ __forceinline__ void gemm_core(const float* __restrict__ A,
                                          const float* __restrict__ Bt,
                                          float* __restrict__ outp, int head_out)
{
    __shared__ float As[2][GBM * GPAD];
    __shared__ float Bs[2][GBN * GPAD];

    const int tid = threadIdx.x, lane = tid & 31, wid = tid >> 5;
    const int wm = (wid >> 2) * 64;   // warp m offset (2 warps)
    const int wn = (wid & 3) * 32;    // warp n offset (4 warps)
    const int gi = lane >> 2, tg = lane & 3;

    const int brow = blockIdx.y * GBM, bcol = blockIdx.x * GBN;
    const int lr = tid >> 2;          // loader row 0..63
    const int lc = (tid & 3) * 4;     // loader col

    const float* Ag = A  + (size_t)(brow + lr) * C_ + lc;
    const float* Bg = Bt + (size_t)(bcol + lr) * C_ + lc;

    float acc[4][4][4];
    #pragma unroll
    for (int i = 0; i < 4; i++)
        #pragma unroll
        for (int j = 0; j < 4; j++)
            #pragma unroll
            for (int q = 0; q < 4; q++) acc[i][j][q] = 0.f;

    float4 pa0 = *(const float4*)Ag;
    float4 pa1 = *(const float4*)(Ag + (size_t)64 * C_);
    float4 pb0 = *(const float4*)Bg;
    float4 pb1 = *(const float4*)(Bg + (size_t)64 * C_);

    for (int c = 0; c < NCH; c++) {
        const int cur = c & 1;
        *(float4*)&As[cur][lr * GPAD + lc]        = pa0;
        *(float4*)&As[cur][(lr + 64) * GPAD + lc] = pa1;
        *(float4*)&Bs[cur][lr * GPAD + lc]        = pb0;
        *(float4*)&Bs[cur][(lr + 64) * GPAD + lc] = pb1;
        __syncthreads();
        if (c + 1 < NCH) {
            Ag += GBK; Bg += GBK;
            pa0 = *(const float4*)Ag;
            pa1 = *(const float4*)(Ag + (size_t)64 * C_);
            pb0 = *(const float4*)Bg;
            pb1 = *(const float4*)(Bg + (size_t)64 * C_);
        }
        #pragma unroll
        for (int ks = 0; ks < 2; ks++) {
            const int kb = ks * 8;
            uint32_t af[4][4], bf[4][2];
            #pragma unroll
            for (int ms = 0; ms < 4; ms++) {
                int r = wm + ms * 16 + gi;
                af[ms][0] = fbits(As[cur][r * GPAD + kb + tg]);
                af[ms][1] = fbits(As[cur][(r + 8) * GPAD + kb + tg]);
                af[ms][2] = fbits(As[cur][r * GPAD + kb + tg + 4]);
                af[ms][3] = fbits(As[cur][(r + 8) * GPAD + kb + tg + 4]);
            }
            #pragma unroll
            for (int ns = 0; ns < 4; ns++) {
                int n = wn + ns * 8 + gi;
                bf[ns][0] = fbits(Bs[cur][n * GPAD + kb + tg]);
                bf[ns][1] = fbits(Bs[cur][n * GPAD + kb + tg + 4]);
            }
            #pragma unroll
            for (int ms = 0; ms < 4; ms++)
                #pragma unroll
                for (int ns = 0; ns < 4; ns++)
                    mma_tf32(acc[ms][ns], af[ms], bf[ns]);
        }
    }

    #pragma unroll
    for (int ms = 0; ms < 4; ms++) {
        int r0 = brow + wm + ms * 16 + gi;
        int r1 = r0 + 8;
        #pragma unroll
        for (int ns = 0; ns < 4; ns++) {
            int n = bcol + wn + ns * 8 + tg * 2;
            if (head_out) {
                int h = n >> 6, d0 = n & 63;
                float* p0 = outp + (((size_t)(r0 >> 11) * NH_ + h) * T_ + (r0 & (T_-1))) * HS_ + d0;
                float* p1 = outp + (((size_t)(r1 >> 11) * NH_ + h) * T_ + (r1 & (T_-1))) * HS_ + d0;
                *(float2*)p0 = make_float2(rn_tf32(acc[ms][ns][0]), rn_tf32(acc[ms][ns][1]));
                *(float2*)p1 = make_float2(rn_tf32(acc[ms][ns][2]), rn_tf32(acc[ms][ns][3]));
            } else {
                *(float2*)(outp + (size_t)r0 * C_ + n) = make_float2(acc[ms][ns][0], acc[ms][ns][1]);
                *(float2*)(outp + (size_t)r1 * C_ + n) = make_float2(acc[ms][ns][2], acc[ms][ns][3]);
            }
        }
    }
}

__global__ __launch_bounds__(256, 2) void gemm_qkv_tc() {
    const int z = blockIdx.z;
    const float* Bt = g_wt + ((size_t)z << 20);
    float* o = (z == 0) ? g_q : (z == 1) ? g_k : g_v;
    gemm_core(g_xt, Bt, o, 1);
}
__global__ __launch_bounds__(256, 2) void gemm_proj_tc(float* __restrict__ out) {
    gemm_core(g_y, g_wt + ((size_t)3 << 20), out, 0);
}

// ---------------- flash attention with tf32 mma.sync ------------------------
// CTA = 128 thr (4 warps), one 64-row q tile of one head. Warp w owns rows
// w*16..w*16+15. Smem pads chosen conflict-free for fragment gather patterns.
#define PQ 68
#define PK 68
#define PVp 72
#define PP 68
#define ASMEM ((64*PQ + 64*PK + 64*PVp + 64*PP) * 4)   // 70656 B
#define L2E 1.4426950408889634f

__global__ __launch_bounds__(128) void attn_mma()
{
    extern __shared__ float sm[];
    float* Qs = sm;
    float* Ks = Qs + 64 * PQ;
    float* Vs = Ks + 64 * PK;
    float* Ps = Vs + 64 * PVp;

    const int qt = blockIdx.x, bh = blockIdx.y;
    const int tid = threadIdx.x, wid = tid >> 5, lane = tid & 31;
    const int gi = lane >> 2, tg = lane & 3;
    const int wm = wid * 16;

    const float* Qg = g_q + ((size_t)bh * T_ + (size_t)qt * 64) * HS_;
    const float* Kg = g_k + (size_t)bh * T_ * HS_;
    const float* Vg = g_v + (size_t)bh * T_ * HS_;

    // load Q tile (scale by 1/sqrt(HS) = 0.125, exact in tf32)
    #pragma unroll
    for (int i = 0; i < 8; i++) {
        int r = (tid >> 4) + i * 8, c4 = (tid & 15) * 4;
        float4 v = *(const float4*)(Qg + r * 64 + c4);
        v.x *= 0.125f; v.y *= 0.125f; v.z *= 0.125f; v.w *= 0.125f;
        *(float4*)&Qs[r * PQ + c4] = v;
    }

    float accO[8][4];
    #pragma unroll
    for (int ns = 0; ns < 8; ns++)
        #pragma unroll
        for (int q = 0; q < 4; q++) accO[ns][q] = 0.f;
    float m0 = -1e30f, m1 = -1e30f, l0 = 0.f, l1 = 0.f;

    const int q0 = qt * 64 + wm + gi, q1 = q0 + 8;

    for (int kt = 0; kt <= qt; kt++) {
        __syncthreads();
        #pragma unroll
        for (int i = 0; i < 8; i++) {
            int r = (tid >> 4) + i * 8, c4 = (tid & 15) * 4;
            *(float4*)&Ks[r * PK + c4]  = *(const float4*)(Kg + ((size_t)kt * 64 + r) * 64 + c4);
            *(float4*)&Vs[r * PVp + c4] = *(const float4*)(Vg + ((size_t)kt * 64 + r) * 64 + c4);
        }
        __syncthreads();

        // S = Q K^T  (warp's 16 x 64 scores)
        float sacc[8][4];
        #pragma unroll
        for (int ns = 0; ns < 8; ns++)
            #pragma unroll
            for (int q = 0; q < 4; q++) sacc[ns][q] = 0.f;
        #pragma unroll
        for (int ks = 0; ks < 8; ks++) {
            int kb = ks * 8;
            uint32_t a[4];
            a[0] = fbits(Qs[(wm + gi) * PQ + kb + tg]);
            a[1] = fbits(Qs[(wm + gi + 8) * PQ + kb + tg]);
            a[2] = fbits(Qs[(wm + gi) * PQ + kb + tg + 4]);
            a[3] = fbits(Qs[(wm + gi + 8) * PQ + kb + tg + 4]);
            #pragma unroll
            for (int ns = 0; ns < 8; ns++) {
                uint32_t b[2];
                b[0] = fbits(Ks[(ns * 8 + gi) * PK + kb + tg]);
                b[1] = fbits(Ks[(ns * 8 + gi) * PK + kb + tg + 4]);
                mma_tf32(sacc[ns], a, b);
            }
        }

        if (kt == qt) {   // causal mask on diagonal tile
            #pragma unroll
            for (int ns = 0; ns < 8; ns++) {
                int c0 = kt * 64 + ns * 8 + tg * 2;
                if (c0     > q0) sacc[ns][0] = -1e30f;
                if (c0 + 1 > q0) sacc[ns][1] = -1e30f;
                if (c0     > q1) sacc[ns][2] = -1e30f;
                if (c0 + 1 > q1) sacc[ns][3] = -1e30f;
            }
        }

        // online softmax
        float tm0 = -1e30f, tm1 = -1e30f;
        #pragma unroll
        for (int ns = 0; ns < 8; ns++) {
            tm0 = fmaxf(tm0, fmaxf(sacc[ns][0], sacc[ns][1]));
            tm1 = fmaxf(tm1, fmaxf(sacc[ns][2], sacc[ns][3]));
        }
        tm0 = fmaxf(tm0, __shfl_xor_sync(0xffffffffu, tm0, 1));
        tm0 = fmaxf(tm0, __shfl_xor_sync(0xffffffffu, tm0, 2));
        tm1 = fmaxf(tm1, __shfl_xor_sync(0xffffffffu, tm1, 1));
        tm1 = fmaxf(tm1, __shfl_xor_sync(0xffffffffu, tm1, 2));
        float nm0 = fmaxf(m0, tm0), nm1 = fmaxf(m1, tm1);
        float f0 = ex2((m0 - nm0) * L2E), f1 = ex2((m1 - nm1) * L2E);
        m0 = nm0; m1 = nm1;

        float ps0 = 0.f, ps1 = 0.f;
        #pragma unroll
        for (int ns = 0; ns < 8; ns++) {
            float p0 = ex2((sacc[ns][0] - nm0) * L2E);
            float p1 = ex2((sacc[ns][1] - nm0) * L2E);
            float p2 = ex2((sacc[ns][2] - nm1) * L2E);
            float p3 = ex2((sacc[ns][3] - nm1) * L2E);
            ps0 += p0 + p1; ps1 += p2 + p3;
            int c0 = ns * 8 + tg * 2;
            Ps[(wm + gi) * PP + c0]       = rn_tf32(p0);
            Ps[(wm + gi) * PP + c0 + 1]   = rn_tf32(p1);
            Ps[(wm + gi + 8) * PP + c0]     = rn_tf32(p2);
            Ps[(wm + gi + 8) * PP + c0 + 1] = rn_tf32(p3);
        }
        ps0 += __shfl_xor_sync(0xffffffffu, ps0, 1);
        ps0 += __shfl_xor_sync(0xffffffffu, ps0, 2);
        ps1 += __shfl_xor_sync(0xffffffffu, ps1, 1);
        ps1 += __shfl_xor_sync(0xffffffffu, ps1, 2);
        l0 = l0 * f0 + ps0;
        l1 = l1 * f1 + ps1;
        #pragma unroll
        for (int ns = 0; ns < 8; ns++) {
            accO[ns][0] *= f0; accO[ns][1] *= f0;
            accO[ns][2] *= f1; accO[ns][3] *= f1;
        }
        __syncwarp();   // Ps visible within warp (warp-private region)

        // O += P V
        #pragma unroll
        for (int ks = 0; ks < 8; ks++) {
            int kb = ks * 8;
            uint32_t a[4];
            a[0] = fbits(Ps[(wm + gi) * PP + kb + tg]);
            a[1] = fbits(Ps[(wm + gi + 8) * PP + kb + tg]);
            a[2] = fbits(Ps[(wm + gi) * PP + kb + tg + 4]);
            a[3] = fbits(Ps[(wm + gi + 8) * PP + kb + tg + 4]);
            #pragma unroll
            for (int ns = 0; ns < 8; ns++) {
                uint32_t b[2];
                b[0] = fbits(Vs[(kb + tg) * PVp + ns * 8 + gi]);
                b[1] = fbits(Vs[(kb + tg + 4) * PVp + ns * 8 + gi]);
                mma_tf32(accO[ns], a, b);
            }
        }
        __syncwarp();   // PV reads done before next tile's Ps writes
    }

    const float i0 = 1.f / l0, i1 = 1.f / l1;
    const int b = bh >> 4, h = bh & (NH_ - 1);
    float* y0 = g_y + ((size_t)b * T_ + q0) * C_ + h * HS_;
    float* y1 = g_y + ((size_t)b * T_ + q1) * C_ + h * HS_;
    #pragma unroll
    for (int ns = 0; ns < 8; ns++) {
        int c0 = ns * 8 + tg * 2;
        *(float2*)(y0 + c0) = make_float2(rn_tf32(accO[ns][0] * i0), rn_tf32(accO[ns][1] * i0));
        *(float2*)(y1 + c0) = make_float2(rn_tf32(accO[ns][2] * i1), rn_tf32(accO[ns][3] * i1));
    }
}

// ---------------------------------------------------------------------------
extern "C" void kernel_launch(void* const* d_in, const int* in_sizes, int n_in,
                              void* d_out, int out_size)
{
    (void)in_sizes; (void)n_in; (void)out_size;
    const float* x  = (const float*)d_in[0];
    const float* Wk = (const float*)d_in[1];
    const float* Wq = (const float*)d_in[2];
    const float* Wv = (const float*)d_in[3];
    const float* Wp = (const float*)d_in[4];
    float* out = (float*)d_out;

    static int attr_done = 0;
    if (!attr_done) {
        cudaFuncSetAttribute(attn_mma, cudaFuncAttributeMaxDynamicSharedMemorySize, ASMEM);
        attr_done = 1;
    }

    round_x_kernel<<<2048, 256>>>(x);
    transpose_w_kernel<<<dim3(32, 32, 4), dim3(32, 8)>>>(Wq, Wk, Wv, Wp);

    gemm_qkv_tc<<<dim3(C_ / GBN, M_ / GBM, 3), 256>>>();

    attn_mma<<<dim3(T_ / 64, B_ * NH_), 128, ASMEM>>>();

    gemm_proj_tc<<<dim3(C_ / GBN, M_ / GBM, 1), 256>>>(out);
}

// round 6
// speedup vs baseline: 1.0978x; 1.0978x over previous
#include <cuda_runtime.h>
#include <cstdint>

#define B_  4
#define T_  2048
#define C_  1024
#define NH_ 16
#define HS_ 64
#define M_  (B_*T_)   // 8192

// ---------------- scratch (static device arrays: allocation-free) ----------
__device__ float g_q [(size_t)M_ * C_];   // [B,H,T,HS] tf32-rounded
__device__ float g_k [(size_t)M_ * C_];
__device__ float g_v [(size_t)M_ * C_];
__device__ float g_y [(size_t)M_ * C_];   // [B,T,C]   tf32-rounded
__device__ float g_xt[(size_t)M_ * C_];   // x rounded to tf32
__device__ float g_wt[(size_t)4 * C_ * C_]; // W^T (K-major, tf32): q,k,v,p

// ---------------- helpers ---------------------------------------------------
__device__ __forceinline__ float rn_tf32(float x) {
    uint32_t u;
    asm("cvt.rna.tf32.f32 %0, %1;" : "=r"(u) : "f"(x));
    return __uint_as_float(u);
}
__device__ __forceinline__ uint32_t fbits(float f) { return __float_as_uint(f); }
__device__ __forceinline__ float ex2(float x) {
    float y; asm("ex2.approx.f32 %0, %1;" : "=f"(y) : "f"(x)); return y;
}
__device__ __forceinline__ void mma_tf32(float* d, const uint32_t* a, const uint32_t* b) {
    asm volatile("mma.sync.aligned.m16n8k8.row.col.f32.tf32.tf32.f32 "
                 "{%0,%1,%2,%3}, {%4,%5,%6,%7}, {%8,%9}, {%0,%1,%2,%3};"
                 : "+f"(d[0]), "+f"(d[1]), "+f"(d[2]), "+f"(d[3])
                 : "r"(a[0]), "r"(a[1]), "r"(a[2]), "r"(a[3]), "r"(b[0]), "r"(b[1]));
}

// ---------------- prepass: round x to tf32 ---------------------------------
__global__ __launch_bounds__(256) void round_x_kernel(const float* __restrict__ x) {
    size_t i0 = ((size_t)blockIdx.x * 256 + threadIdx.x) * 4;
    const size_t stride = (size_t)gridDim.x * 256 * 4;
    for (int r = 0; r < 4; r++) {
        float4 v = *(const float4*)(x + i0);
        v.x = rn_tf32(v.x); v.y = rn_tf32(v.y); v.z = rn_tf32(v.z); v.w = rn_tf32(v.w);
        *(float4*)(g_xt + i0) = v;
        i0 += stride;
    }
}

// ---------------- prepass: transpose + round W -> g_wt[slot][n][k] ---------
__global__ __launch_bounds__(256) void transpose_w_kernel(const float* __restrict__ Wq,
                                                          const float* __restrict__ Wk,
                                                          const float* __restrict__ Wv,
                                                          const float* __restrict__ Wp) {
    __shared__ float tile[32][33];
    const int z = blockIdx.z;
    const float* src = (z == 0) ? Wq : (z == 1) ? Wk : (z == 2) ? Wv : Wp;
    float* dst = g_wt + ((size_t)z << 20);
    int x = blockIdx.x * 32 + threadIdx.x;   // n
    int y = blockIdx.y * 32 + threadIdx.y;   // k
    #pragma unroll
    for (int i = 0; i < 32; i += 8)
        tile[threadIdx.y + i][threadIdx.x] = src[(size_t)(y + i) * C_ + x];
    __syncthreads();
    int xo = blockIdx.y * 32 + threadIdx.x;  // k
    int yo = blockIdx.x * 32 + threadIdx.y;  // n
    #pragma unroll
    for (int i = 0; i < 32; i += 8)
        dst[(size_t)(yo + i) * C_ + xo] = rn_tf32(tile[threadIdx.x][threadIdx.y + i]);
}

// ---------------- tf32 mma.sync GEMM: 128x128 block, 64x64 warp tile --------
// out[m,n] = sum_k A[m,k] * Bt[n,k]; 128 threads (4 warps 2x2), k-chunk 16
#define GBM 128
#define GBN 128
#define GBK 16
#define GPAD 20
#define NCH  (C_ / GBK)   // 64

__device__ __forceinline__ void gemm_core(const float* __restrict__ A,
                                          const float* __restrict__ Bt,
                                          float* __restrict__ outp, int head_out)
{
    __shared__ float As[2][GBM * GPAD];
    __shared__ float Bs[2][GBN * GPAD];

    const int tid = threadIdx.x, lane = tid & 31, wid = tid >> 5;
    const int wm = (wid >> 1) * 64;   // warp m offset
    const int wn = (wid & 1) * 64;    // warp n offset
    const int gi = lane >> 2, tg = lane & 3;

    const int brow = blockIdx.y * GBM, bcol = blockIdx.x * GBN;
    const int lr = tid >> 2;          // loader row 0..31
    const int lc = (tid & 3) * 4;     // loader col

    const float* Ag = A  + (size_t)(brow + lr) * C_ + lc;
    const float* Bg = Bt + (size_t)(bcol + lr) * C_ + lc;

    float acc[4][8][4];
    #pragma unroll
    for (int i = 0; i < 4; i++)
        #pragma unroll
        for (int j = 0; j < 8; j++)
            #pragma unroll
            for (int q = 0; q < 4; q++) acc[i][j][q] = 0.f;

    float4 pa[4], pb[4];
    #pragma unroll
    for (int p = 0; p < 4; p++) {
        pa[p] = *(const float4*)(Ag + (size_t)(p * 32) * C_);
        pb[p] = *(const float4*)(Bg + (size_t)(p * 32) * C_);
    }

    for (int c = 0; c < NCH; c++) {
        const int cur = c & 1;
        #pragma unroll
        for (int p = 0; p < 4; p++) {
            *(float4*)&As[cur][(lr + p * 32) * GPAD + lc] = pa[p];
            *(float4*)&Bs[cur][(lr + p * 32) * GPAD + lc] = pb[p];
        }
        __syncthreads();
        if (c + 1 < NCH) {
            Ag += GBK; Bg += GBK;
            #pragma unroll
            for (int p = 0; p < 4; p++) {
                pa[p] = *(const float4*)(Ag + (size_t)(p * 32) * C_);
                pb[p] = *(const float4*)(Bg + (size_t)(p * 32) * C_);
            }
        }
        #pragma unroll
        for (int ks = 0; ks < 2; ks++) {
            const int kb = ks * 8;
            uint32_t af[4][4], bf[8][2];
            #pragma unroll
            for (int ms = 0; ms < 4; ms++) {
                int r = wm + ms * 16 + gi;
                af[ms][0] = fbits(As[cur][r * GPAD + kb + tg]);
                af[ms][1] = fbits(As[cur][(r + 8) * GPAD + kb + tg]);
                af[ms][2] = fbits(As[cur][r * GPAD + kb + tg + 4]);
                af[ms][3] = fbits(As[cur][(r + 8) * GPAD + kb + tg + 4]);
            }
            #pragma unroll
            for (int ns = 0; ns < 8; ns++) {
                int n = wn + ns * 8 + gi;
                bf[ns][0] = fbits(Bs[cur][n * GPAD + kb + tg]);
                bf[ns][1] = fbits(Bs[cur][n * GPAD + kb + tg + 4]);
            }
            #pragma unroll
            for (int ms = 0; ms < 4; ms++)
                #pragma unroll
                for (int ns = 0; ns < 8; ns++)
                    mma_tf32(acc[ms][ns], af[ms], bf[ns]);
        }
    }

    #pragma unroll
    for (int ms = 0; ms < 4; ms++) {
        int r0 = brow + wm + ms * 16 + gi;
        int r1 = r0 + 8;
        #pragma unroll
        for (int ns = 0; ns < 8; ns++) {
            int n = bcol + wn + ns * 8 + tg * 2;
            if (head_out) {
                int h = n >> 6, d0 = n & 63;
                float* p0 = outp + (((size_t)(r0 >> 11) * NH_ + h) * T_ + (r0 & (T_-1))) * HS_ + d0;
                float* p1 = outp + (((size_t)(r1 >> 11) * NH_ + h) * T_ + (r1 & (T_-1))) * HS_ + d0;
                *(float2*)p0 = make_float2(rn_tf32(acc[ms][ns][0]), rn_tf32(acc[ms][ns][1]));
                *(float2*)p1 = make_float2(rn_tf32(acc[ms][ns][2]), rn_tf32(acc[ms][ns][3]));
            } else {
                *(float2*)(outp + (size_t)r0 * C_ + n) = make_float2(acc[ms][ns][0], acc[ms][ns][1]);
                *(float2*)(outp + (size_t)r1 * C_ + n) = make_float2(acc[ms][ns][2], acc[ms][ns][3]);
            }
        }
    }
}

__global__ __launch_bounds__(128, 2) void gemm_qkv_tc() {
    const int z = blockIdx.z;
    const float* Bt = g_wt + ((size_t)z << 20);
    float* o = (z == 0) ? g_q : (z == 1) ? g_k : g_v;
    gemm_core(g_xt, Bt, o, 1);
}
__global__ __launch_bounds__(128, 2) void gemm_proj_tc(float* __restrict__ out) {
    gemm_core(g_y, g_wt + ((size_t)3 << 20), out, 0);
}

// ---------------- flash attention: q-tile 128, 4 warps x 32 rows ------------
// P held in registers; C-layout -> A-layout via quad shuffles (no Ps smem).
#define AQT 128
#define AKT 64
#define PQ 68
#define PK 68
#define PVp 72
#define ASMEM ((AQT*PQ + AKT*PK + AKT*PVp) * 4)   // 70656 B
#define L2E 1.4426950408889634f

__global__ __launch_bounds__(128) void attn_mma()
{
    extern __shared__ float sm[];
    float* Qs = sm;                    // [128][PQ]
    float* Ks = Qs + AQT * PQ;         // [64][PK]
    float* Vs = Ks + AKT * PK;         // [64][PVp]

    const int qt = blockIdx.x, bh = blockIdx.y;
    const int tid = threadIdx.x, wid = tid >> 5, lane = tid & 31;
    const int gi = lane >> 2, tg = lane & 3;
    const int wm = wid * 32;

    const float* Qg = g_q + ((size_t)bh * T_ + (size_t)qt * AQT) * HS_;
    const float* Kg = g_k + (size_t)bh * T_ * HS_;
    const float* Vg = g_v + (size_t)bh * T_ * HS_;

    // load Q tile (scale by 1/sqrt(HS)=0.125, exact in tf32)
    #pragma unroll
    for (int i = 0; i < 16; i++) {
        int r = (tid >> 4) + i * 8, c4 = (tid & 15) * 4;
        float4 v = *(const float4*)(Qg + r * 64 + c4);
        v.x *= 0.125f; v.y *= 0.125f; v.z *= 0.125f; v.w *= 0.125f;
        *(float4*)&Qs[r * PQ + c4] = v;
    }

    float accO[2][8][4];
    #pragma unroll
    for (int ms = 0; ms < 2; ms++)
        #pragma unroll
        for (int ns = 0; ns < 8; ns++)
            #pragma unroll
            for (int q = 0; q < 4; q++) accO[ms][ns][q] = 0.f;
    float mx[2][2] = {{-1e30f, -1e30f}, {-1e30f, -1e30f}};
    float li[2][2] = {{0.f, 0.f}, {0.f, 0.f}};

    const int src_a = (lane & 0x1C) | (tg >> 1);
    const int src_b = src_a + 2;
    const int kt_end = 2 * qt + 1;

    for (int kt = 0; kt <= kt_end; kt++) {
        __syncthreads();
        #pragma unroll
        for (int i = 0; i < 8; i++) {
            int r = (tid >> 4) + i * 8, c4 = (tid & 15) * 4;
            *(float4*)&Ks[r * PK + c4]  = *(const float4*)(Kg + ((size_t)kt * AKT + r) * 64 + c4);
            *(float4*)&Vs[r * PVp + c4] = *(const float4*)(Vg + ((size_t)kt * AKT + r) * 64 + c4);
        }
        __syncthreads();
        if (kt * AKT > qt * AQT + wm + 31) continue;   // warp fully masked

        // ---- S = Q K^T : two 16x64 blocks per warp ----
        float sacc[2][8][4];
        #pragma unroll
        for (int ms = 0; ms < 2; ms++)
            #pragma unroll
            for (int ns = 0; ns < 8; ns++)
                #pragma unroll
                for (int q = 0; q < 4; q++) sacc[ms][ns][q] = 0.f;

        #pragma unroll
        for (int ks = 0; ks < 8; ks++) {
            const int kb = ks * 8;
            uint32_t a[2][4];
            #pragma unroll
            for (int ms = 0; ms < 2; ms++) {
                int r = wm + ms * 16 + gi;
                a[ms][0] = fbits(Qs[r * PQ + kb + tg]);
                a[ms][1] = fbits(Qs[(r + 8) * PQ + kb + tg]);
                a[ms][2] = fbits(Qs[r * PQ + kb + tg + 4]);
                a[ms][3] = fbits(Qs[(r + 8) * PQ + kb + tg + 4]);
            }
            #pragma unroll
            for (int ns = 0; ns < 8; ns++) {
                uint32_t b[2];
                b[0] = fbits(Ks[(ns * 8 + gi) * PK + kb + tg]);
                b[1] = fbits(Ks[(ns * 8 + gi) * PK + kb + tg + 4]);
                mma_tf32(sacc[0][ns], a[0], b);
                mma_tf32(sacc[1][ns], a[1], b);
            }
        }

        if (kt >= 2 * qt) {   // diagonal region: causal mask
            #pragma unroll
            for (int ms = 0; ms < 2; ms++) {
                int r0 = qt * AQT + wm + ms * 16 + gi, r1 = r0 + 8;
                #pragma unroll
                for (int ns = 0; ns < 8; ns++) {
                    int c0 = kt * AKT + ns * 8 + tg * 2;
                    if (c0     > r0) sacc[ms][ns][0] = -1e30f;
                    if (c0 + 1 > r0) sacc[ms][ns][1] = -1e30f;
                    if (c0     > r1) sacc[ms][ns][2] = -1e30f;
                    if (c0 + 1 > r1) sacc[ms][ns][3] = -1e30f;
                }
            }
        }

        // ---- online softmax; overwrite sacc with tf32-rounded P ----
        #pragma unroll
        for (int ms = 0; ms < 2; ms++) {
            float tm0 = -1e30f, tm1 = -1e30f;
            #pragma unroll
            for (int ns = 0; ns < 8; ns++) {
                tm0 = fmaxf(tm0, fmaxf(sacc[ms][ns][0], sacc[ms][ns][1]));
                tm1 = fmaxf(tm1, fmaxf(sacc[ms][ns][2], sacc[ms][ns][3]));
            }
            tm0 = fmaxf(tm0, __shfl_xor_sync(0xffffffffu, tm0, 1));
            tm0 = fmaxf(tm0, __shfl_xor_sync(0xffffffffu, tm0, 2));
            tm1 = fmaxf(tm1, __shfl_xor_sync(0xffffffffu, tm1, 1));
            tm1 = fmaxf(tm1, __shfl_xor_sync(0xffffffffu, tm1, 2));
            float nm0 = fmaxf(mx[ms][0], tm0), nm1 = fmaxf(mx[ms][1], tm1);
            float f0 = ex2((mx[ms][0] - nm0) * L2E);
            float f1 = ex2((mx[ms][1] - nm1) * L2E);
            mx[ms][0] = nm0; mx[ms][1] = nm1;

            float ps0 = 0.f, ps1 = 0.f;
            #pragma unroll
            for (int ns = 0; ns < 8; ns++) {
                float p0 = ex2((sacc[ms][ns][0] - nm0) * L2E);
                float p1 = ex2((sacc[ms][ns][1] - nm0) * L2E);
                float p2 = ex2((sacc[ms][ns][2] - nm1) * L2E);
                float p3 = ex2((sacc[ms][ns][3] - nm1) * L2E);
                ps0 += p0 + p1; ps1 += p2 + p3;
                sacc[ms][ns][0] = rn_tf32(p0);
                sacc[ms][ns][1] = rn_tf32(p1);
                sacc[ms][ns][2] = rn_tf32(p2);
                sacc[ms][ns][3] = rn_tf32(p3);
            }
            ps0 += __shfl_xor_sync(0xffffffffu, ps0, 1);
            ps0 += __shfl_xor_sync(0xffffffffu, ps0, 2);
            ps1 += __shfl_xor_sync(0xffffffffu, ps1, 1);
            ps1 += __shfl_xor_sync(0xffffffffu, ps1, 2);
            li[ms][0] = li[ms][0] * f0 + ps0;
            li[ms][1] = li[ms][1] * f1 + ps1;
            #pragma unroll
            for (int ns = 0; ns < 8; ns++) {
                accO[ms][ns][0] *= f0; accO[ms][ns][1] *= f0;
                accO[ms][ns][2] *= f1; accO[ms][ns][3] *= f1;
            }
        }

        // ---- O += P V ; P A-fragments via quad shuffles from C-layout ----
        #pragma unroll
        for (int ks = 0; ks < 8; ks++) {
            const int kb = ks * 8;
            uint32_t a[2][4];
            #pragma unroll
            for (int ms = 0; ms < 2; ms++) {
                float v0 = __shfl_sync(0xffffffffu, sacc[ms][ks][0], src_a);
                float v1 = __shfl_sync(0xffffffffu, sacc[ms][ks][1], src_a);
                a[ms][0] = fbits((tg & 1) ? v1 : v0);
                float v2 = __shfl_sync(0xffffffffu, sacc[ms][ks][2], src_a);
                float v3 = __shfl_sync(0xffffffffu, sacc[ms][ks][3], src_a);
                a[ms][1] = fbits((tg & 1) ? v3 : v2);
                float v4 = __shfl_sync(0xffffffffu, sacc[ms][ks][0], src_b);
                float v5 = __shfl_sync(0xffffffffu, sacc[ms][ks][1], src_b);
                a[ms][2] = fbits((tg & 1) ? v5 : v4);
                float v6 = __shfl_sync(0xffffffffu, sacc[ms][ks][2], src_b);
                float v7 = __shfl_sync(0xffffffffu, sacc[ms][ks][3], src_b);
                a[ms][3] = fbits((tg & 1) ? v7 : v6);
            }
            #pragma unroll
            for (int ns = 0; ns < 8; ns++) {
                uint32_t b[2];
                b[0] = fbits(Vs[(kb + tg) * PVp + ns * 8 + gi]);
                b[1] = fbits(Vs[(kb + tg + 4) * PVp + ns * 8 + gi]);
                mma_tf32(accO[0][ns], a[0], b);
                mma_tf32(accO[1][ns], a[1], b);
            }
        }
    }

    // ---- write y (tf32-rounded for proj GEMM) ----
    const int b = bh >> 4, h = bh & (NH_ - 1);
    #pragma unroll
    for (int ms = 0; ms < 2; ms++) {
        float i0 = 1.f / li[ms][0], i1 = 1.f / li[ms][1];
        int q0 = qt * AQT + wm + ms * 16 + gi, q1 = q0 + 8;
        float* y0 = g_y + ((size_t)b * T_ + q0) * C_ + h * HS_;
        float* y1 = g_y + ((size_t)b * T_ + q1) * C_ + h * HS_;
        #pragma unroll
        for (int ns = 0; ns < 8; ns++) {
            int c0 = ns * 8 + tg * 2;
            *(float2*)(y0 + c0) = make_float2(rn_tf32(accO[ms][ns][0] * i0),
                                              rn_tf32(accO[ms][ns][1] * i0));
            *(float2*)(y1 + c0) = make_float2(rn_tf32(accO[ms][ns][2] * i1),
                                              rn_tf32(accO[ms][ns][3] * i1));
        }
    }
}

// ---------------------------------------------------------------------------
extern "C" void kernel_launch(void* const* d_in, const int* in_sizes, int n_in,
                              void* d_out, int out_size)
{
    (void)in_sizes; (void)n_in; (void)out_size;
    const float* x  = (const float*)d_in[0];
    const float* Wk = (const float*)d_in[1];
    const float* Wq = (const float*)d_in[2];
    const float* Wv = (const float*)d_in[3];
    const float* Wp = (const float*)d_in[4];
    float* out = (float*)d_out;

    static int attr_done = 0;
    if (!attr_done) {
        cudaFuncSetAttribute(attn_mma, cudaFuncAttributeMaxDynamicSharedMemorySize, ASMEM);
        attr_done = 1;
    }

    round_x_kernel<<<2048, 256>>>(x);
    transpose_w_kernel<<<dim3(32, 32, 4), dim3(32, 8)>>>(Wq, Wk, Wv, Wp);

    gemm_qkv_tc<<<dim3(C_ / GBN, M_ / GBM, 3), 128>>>();

    attn_mma<<<dim3(T_ / AQT, B_ * NH_), 128, ASMEM>>>();

    gemm_proj_tc<<<dim3(C_ / GBN, M_ / GBM, 1), 128>>>(out);
}

// round 7
// speedup vs baseline: 1.1688x; 1.0647x over previous
#include <cuda_runtime.h>
#include <cstdint>

#define B_  4
#define T_  2048
#define C_  1024
#define NH_ 16
#define HS_ 64
#define M_  (B_*T_)   // 8192

// ---------------- scratch (static device arrays: allocation-free) ----------
__device__ float g_q [(size_t)M_ * C_];   // [B,H,T,HS] tf32-rounded
__device__ float g_k [(size_t)M_ * C_];
__device__ float g_v [(size_t)M_ * C_];
__device__ float g_y [(size_t)M_ * C_];   // [B,T,C]   tf32-rounded
__device__ float g_xt[(size_t)M_ * C_];   // x rounded to tf32
__device__ float g_wt[(size_t)4 * C_ * C_]; // W^T (K-major, tf32): q,k,v,p

// ---------------- helpers ---------------------------------------------------
__device__ __forceinline__ float rn_tf32(float x) {
    uint32_t u;
    asm("cvt.rna.tf32.f32 %0, %1;" : "=r"(u) : "f"(x));
    return __uint_as_float(u);
}
__device__ __forceinline__ uint32_t fbits(float f) { return __float_as_uint(f); }
__device__ __forceinline__ float ex2(float x) {
    float y; asm("ex2.approx.f32 %0, %1;" : "=f"(y) : "f"(x)); return y;
}
__device__ __forceinline__ void mma_tf32(float* d, const uint32_t* a, const uint32_t* b) {
    asm volatile("mma.sync.aligned.m16n8k8.row.col.f32.tf32.tf32.f32 "
                 "{%0,%1,%2,%3}, {%4,%5,%6,%7}, {%8,%9}, {%0,%1,%2,%3};"
                 : "+f"(d[0]), "+f"(d[1]), "+f"(d[2]), "+f"(d[3])
                 : "r"(a[0]), "r"(a[1]), "r"(a[2]), "r"(a[3]), "r"(b[0]), "r"(b[1]));
}
__device__ __forceinline__ uint32_t smem_u32(const void* p) {
    uint32_t a;
    asm("{ .reg .u64 t; cvta.to.shared.u64 t, %1; cvt.u32.u64 %0, t; }" : "=r"(a) : "l"(p));
    return a;
}
__device__ __forceinline__ void cp16(uint32_t dst, const void* src) {
    asm volatile("cp.async.cg.shared.global [%0], [%1], 16;" :: "r"(dst), "l"(src));
}
#define CP_COMMIT() asm volatile("cp.async.commit_group;" ::: "memory")
#define CP_WAIT1()  asm volatile("cp.async.wait_group 1;" ::: "memory")

// ---------------- prepass: round x to tf32 ---------------------------------
__global__ __launch_bounds__(256) void round_x_kernel(const float* __restrict__ x) {
    size_t i0 = ((size_t)blockIdx.x * 256 + threadIdx.x) * 4;
    const size_t stride = (size_t)gridDim.x * 256 * 4;
    for (int r = 0; r < 4; r++) {
        float4 v = *(const float4*)(x + i0);
        v.x = rn_tf32(v.x); v.y = rn_tf32(v.y); v.z = rn_tf32(v.z); v.w = rn_tf32(v.w);
        *(float4*)(g_xt + i0) = v;
        i0 += stride;
    }
}

// ---------------- prepass: transpose + round W -> g_wt[slot][n][k] ---------
__global__ __launch_bounds__(256) void transpose_w_kernel(const float* __restrict__ Wq,
                                                          const float* __restrict__ Wk,
                                                          const float* __restrict__ Wv,
                                                          const float* __restrict__ Wp) {
    __shared__ float tile[32][33];
    const int z = blockIdx.z;
    const float* src = (z == 0) ? Wq : (z == 1) ? Wk : (z == 2) ? Wv : Wp;
    float* dst = g_wt + ((size_t)z << 20);
    int x = blockIdx.x * 32 + threadIdx.x;   // n
    int y = blockIdx.y * 32 + threadIdx.y;   // k
    #pragma unroll
    for (int i = 0; i < 32; i += 8)
        tile[threadIdx.y + i][threadIdx.x] = src[(size_t)(y + i) * C_ + x];
    __syncthreads();
    int xo = blockIdx.y * 32 + threadIdx.x;  // k
    int yo = blockIdx.x * 32 + threadIdx.y;  // n
    #pragma unroll
    for (int i = 0; i < 32; i += 8)
        dst[(size_t)(yo + i) * C_ + xo] = rn_tf32(tile[threadIdx.x][threadIdx.y + i]);
}

// ---------------- tf32 mma.sync GEMM: 128x128 block, 64x64 warp tile --------
// 3-stage cp.async pipeline; 128 threads (4 warps 2x2); k-chunk 16.
#define GBM 128
#define GBN 128
#define GBK 16
#define GPAD 20
#define NCH  (C_ / GBK)   // 64
#define GSS  ((GBM + GBN) * GPAD)          // floats per stage (5120)
#define GSMEM (3 * GSS * 4)                // 61440 B

__device__ __forceinline__ void gemm_core(const float* __restrict__ A,
                                          const float* __restrict__ Bt,
                                          float* __restrict__ outp, int head_out)
{
    extern __shared__ float gsm[];
    const uint32_t smb = smem_u32(gsm);

    const int tid = threadIdx.x, lane = tid & 31, wid = tid >> 5;
    const int wm = (wid >> 1) * 64;
    const int wn = (wid & 1) * 64;
    const int gi = lane >> 2, tg = lane & 3;

    const int brow = blockIdx.y * GBM, bcol = blockIdx.x * GBN;
    const int lr = tid >> 2;          // 0..31
    const int lc = (tid & 3) * 4;

    const float* Ag = A  + (size_t)(brow + lr) * C_ + lc;
    const float* Bg = Bt + (size_t)(bcol + lr) * C_ + lc;
    const uint32_t sA0 = smb + (uint32_t)(lr * GPAD + lc) * 4;
    const uint32_t sB0 = sA0 + (uint32_t)(GBM * GPAD) * 4;

    float acc[4][8][4];
    #pragma unroll
    for (int i = 0; i < 4; i++)
        #pragma unroll
        for (int j = 0; j < 8; j++)
            #pragma unroll
            for (int q = 0; q < 4; q++) acc[i][j][q] = 0.f;

    // prologue: stages 0,1
    #pragma unroll
    for (int s = 0; s < 2; s++) {
        #pragma unroll
        for (int p = 0; p < 4; p++) {
            cp16(sA0 + (uint32_t)(s * GSS + p * 32 * GPAD) * 4, Ag + (size_t)(p * 32) * C_ + s * GBK);
            cp16(sB0 + (uint32_t)(s * GSS + p * 32 * GPAD) * 4, Bg + (size_t)(p * 32) * C_ + s * GBK);
        }
        CP_COMMIT();
    }

    for (int c = 0; c < NCH; c++) {
        CP_WAIT1();
        __syncthreads();
        const float* Ac = gsm + (c % 3) * GSS;
        const float* Bc = Ac + GBM * GPAD;

        #pragma unroll
        for (int ks = 0; ks < 2; ks++) {
            const int kb = ks * 8;
            uint32_t af[4][4], bf[8][2];
            #pragma unroll
            for (int ms = 0; ms < 4; ms++) {
                int r = wm + ms * 16 + gi;
                af[ms][0] = fbits(Ac[r * GPAD + kb + tg]);
                af[ms][1] = fbits(Ac[(r + 8) * GPAD + kb + tg]);
                af[ms][2] = fbits(Ac[r * GPAD + kb + tg + 4]);
                af[ms][3] = fbits(Ac[(r + 8) * GPAD + kb + tg + 4]);
            }
            #pragma unroll
            for (int ns = 0; ns < 8; ns++) {
                int n = wn + ns * 8 + gi;
                bf[ns][0] = fbits(Bc[n * GPAD + kb + tg]);
                bf[ns][1] = fbits(Bc[n * GPAD + kb + tg + 4]);
            }
            #pragma unroll
            for (int ms = 0; ms < 4; ms++)
                #pragma unroll
                for (int ns = 0; ns < 8; ns++)
                    mma_tf32(acc[ms][ns], af[ms], bf[ns]);
        }
        __syncthreads();
        if (c + 2 < NCH) {
            const int s = (c + 2) % 3, k0 = (c + 2) * GBK;
            #pragma unroll
            for (int p = 0; p < 4; p++) {
                cp16(sA0 + (uint32_t)(s * GSS + p * 32 * GPAD) * 4, Ag + (size_t)(p * 32) * C_ + k0);
                cp16(sB0 + (uint32_t)(s * GSS + p * 32 * GPAD) * 4, Bg + (size_t)(p * 32) * C_ + k0);
            }
        }
        CP_COMMIT();
    }

    #pragma unroll
    for (int ms = 0; ms < 4; ms++) {
        int r0 = brow + wm + ms * 16 + gi;
        int r1 = r0 + 8;
        #pragma unroll
        for (int ns = 0; ns < 8; ns++) {
            int n = bcol + wn + ns * 8 + tg * 2;
            if (head_out) {
                int h = n >> 6, d0 = n & 63;
                float* p0 = outp + (((size_t)(r0 >> 11) * NH_ + h) * T_ + (r0 & (T_-1))) * HS_ + d0;
                float* p1 = outp + (((size_t)(r1 >> 11) * NH_ + h) * T_ + (r1 & (T_-1))) * HS_ + d0;
                *(float2*)p0 = make_float2(rn_tf32(acc[ms][ns][0]), rn_tf32(acc[ms][ns][1]));
                *(float2*)p1 = make_float2(rn_tf32(acc[ms][ns][2]), rn_tf32(acc[ms][ns][3]));
            } else {
                *(float2*)(outp + (size_t)r0 * C_ + n) = make_float2(acc[ms][ns][0], acc[ms][ns][1]);
                *(float2*)(outp + (size_t)r1 * C_ + n) = make_float2(acc[ms][ns][2], acc[ms][ns][3]);
            }
        }
    }
}

__global__ __launch_bounds__(128, 2) void gemm_qkv_tc() {
    const int z = blockIdx.z;
    const float* Bt = g_wt + ((size_t)z << 20);
    float* o = (z == 0) ? g_q : (z == 1) ? g_k : g_v;
    gemm_core(g_xt, Bt, o, 1);
}
__global__ __launch_bounds__(128, 2) void gemm_proj_tc(float* __restrict__ out) {
    gemm_core(g_y, g_wt + ((size_t)3 << 20), out, 0);
}

// ---------------- flash attention: Q in regs, 2-stage cp.async K/V ----------
#define AQT 128
#define AKT 64
#define PQ 68
#define PK 68
#define PVp 72
#define ASS (AKT * PK + AKT * PVp)         // floats per stage (8960)
#define ASMEM (2 * ASS * 4)                // 71680 B
#define L2E 1.4426950408889634f

__global__ __launch_bounds__(128) void attn_mma()
{
    extern __shared__ float sm[];
    const uint32_t smb = smem_u32(sm);

    const int qt = blockIdx.x, bh = blockIdx.y;
    const int tid = threadIdx.x, wid = tid >> 5, lane = tid & 31;
    const int gi = lane >> 2, tg = lane & 3;
    const int wm = wid * 32;

    const float* Qg = g_q + ((size_t)bh * T_ + (size_t)qt * AQT) * HS_;
    const float* Kg = g_k + (size_t)bh * T_ * HS_;
    const float* Vg = g_v + (size_t)bh * T_ * HS_;

    const int kt_end = 2 * qt + 1;

    // loader geometry: 8 rows-groups of 8, c4 = 16B column
    const int ldr = tid >> 4;          // 0..7
    const int ldc = (tid & 15) * 4;    // 0..60

    // ---- prologue: stage0 <- tile 0 (cp.async) ----
    {
        const float* Kt = Kg;
        const float* Vt = Vg;
        #pragma unroll
        for (int i = 0; i < 8; i++) {
            int r = ldr + i * 8;
            cp16(smb + (uint32_t)(r * PK + ldc) * 4,              Kt + r * 64 + ldc);
            cp16(smb + (uint32_t)(AKT * PK + r * PVp + ldc) * 4,  Vt + r * 64 + ldc);
        }
        CP_COMMIT();
    }

    // ---- stage Q into stage-1 region, extract fragments to registers ----
    float* Qtmp = sm + ASS;            // 128*68 = 8704 <= 8960 floats
    #pragma unroll
    for (int i = 0; i < 16; i++) {
        int r = ldr + i * 8;
        float4 v = *(const float4*)(Qg + r * 64 + ldc);
        v.x *= 0.125f; v.y *= 0.125f; v.z *= 0.125f; v.w *= 0.125f;
        *(float4*)&Qtmp[r * PQ + ldc] = v;
    }
    __syncthreads();
    uint32_t aq[8][2][4];
    #pragma unroll
    for (int ks = 0; ks < 8; ks++) {
        const int kb = ks * 8;
        #pragma unroll
        for (int ms = 0; ms < 2; ms++) {
            int r = wm + ms * 16 + gi;
            aq[ks][ms][0] = fbits(Qtmp[r * PQ + kb + tg]);
            aq[ks][ms][1] = fbits(Qtmp[(r + 8) * PQ + kb + tg]);
            aq[ks][ms][2] = fbits(Qtmp[r * PQ + kb + tg + 4]);
            aq[ks][ms][3] = fbits(Qtmp[(r + 8) * PQ + kb + tg + 4]);
        }
    }
    __syncthreads();

    // ---- prologue: stage1 <- tile 1 (always exists: kt_end >= 1) ----
    {
        const float* Kt = Kg + (size_t)AKT * 64;
        const float* Vt = Vg + (size_t)AKT * 64;
        #pragma unroll
        for (int i = 0; i < 8; i++) {
            int r = ldr + i * 8;
            cp16(smb + (uint32_t)(ASS + r * PK + ldc) * 4,                 Kt + r * 64 + ldc);
            cp16(smb + (uint32_t)(ASS + AKT * PK + r * PVp + ldc) * 4,     Vt + r * 64 + ldc);
        }
        CP_COMMIT();
    }

    float accO[2][8][4];
    #pragma unroll
    for (int ms = 0; ms < 2; ms++)
        #pragma unroll
        for (int ns = 0; ns < 8; ns++)
            #pragma unroll
            for (int q = 0; q < 4; q++) accO[ms][ns][q] = 0.f;
    float mx[2][2] = {{-1e30f, -1e30f}, {-1e30f, -1e30f}};
    float li[2][2] = {{0.f, 0.f}, {0.f, 0.f}};

    const int src_a = (lane & 0x1C) | (tg >> 1);
    const int src_b = src_a + 2;

    for (int kt = 0; kt <= kt_end; kt++) {
        CP_WAIT1();
        __syncthreads();
        const float* Kst = sm + (kt & 1) * ASS;
        const float* Vst = Kst + AKT * PK;

        if (kt * AKT <= qt * AQT + wm + 31) {   // warp not fully masked
            // ---- S = Q K^T ----
            float sacc[2][8][4];
            #pragma unroll
            for (int ms = 0; ms < 2; ms++)
                #pragma unroll
                for (int ns = 0; ns < 8; ns++)
                    #pragma unroll
                    for (int q = 0; q < 4; q++) sacc[ms][ns][q] = 0.f;

            #pragma unroll
            for (int ks = 0; ks < 8; ks++) {
                const int kb = ks * 8;
                #pragma unroll
                for (int ns = 0; ns < 8; ns++) {
                    uint32_t b[2];
                    b[0] = fbits(Kst[(ns * 8 + gi) * PK + kb + tg]);
                    b[1] = fbits(Kst[(ns * 8 + gi) * PK + kb + tg + 4]);
                    mma_tf32(sacc[0][ns], aq[ks][0], b);
                    mma_tf32(sacc[1][ns], aq[ks][1], b);
                }
            }

            if (kt >= 2 * qt) {   // diagonal region: causal mask
                #pragma unroll
                for (int ms = 0; ms < 2; ms++) {
                    int r0 = qt * AQT + wm + ms * 16 + gi, r1 = r0 + 8;
                    #pragma unroll
                    for (int ns = 0; ns < 8; ns++) {
                        int c0 = kt * AKT + ns * 8 + tg * 2;
                        if (c0     > r0) sacc[ms][ns][0] = -1e30f;
                        if (c0 + 1 > r0) sacc[ms][ns][1] = -1e30f;
                        if (c0     > r1) sacc[ms][ns][2] = -1e30f;
                        if (c0 + 1 > r1) sacc[ms][ns][3] = -1e30f;
                    }
                }
            }

            // ---- online softmax; sacc -> tf32 P ----
            #pragma unroll
            for (int ms = 0; ms < 2; ms++) {
                float tm0 = -1e30f, tm1 = -1e30f;
                #pragma unroll
                for (int ns = 0; ns < 8; ns++) {
                    tm0 = fmaxf(tm0, fmaxf(sacc[ms][ns][0], sacc[ms][ns][1]));
                    tm1 = fmaxf(tm1, fmaxf(sacc[ms][ns][2], sacc[ms][ns][3]));
                }
                tm0 = fmaxf(tm0, __shfl_xor_sync(0xffffffffu, tm0, 1));
                tm0 = fmaxf(tm0, __shfl_xor_sync(0xffffffffu, tm0, 2));
                tm1 = fmaxf(tm1, __shfl_xor_sync(0xffffffffu, tm1, 1));
                tm1 = fmaxf(tm1, __shfl_xor_sync(0xffffffffu, tm1, 2));
                float nm0 = fmaxf(mx[ms][0], tm0), nm1 = fmaxf(mx[ms][1], tm1);
                float f0 = ex2((mx[ms][0] - nm0) * L2E);
                float f1 = ex2((mx[ms][1] - nm1) * L2E);
                mx[ms][0] = nm0; mx[ms][1] = nm1;

                float ps0 = 0.f, ps1 = 0.f;
                #pragma unroll
                for (int ns = 0; ns < 8; ns++) {
                    float p0 = ex2((sacc[ms][ns][0] - nm0) * L2E);
                    float p1 = ex2((sacc[ms][ns][1] - nm0) * L2E);
                    float p2 = ex2((sacc[ms][ns][2] - nm1) * L2E);
                    float p3 = ex2((sacc[ms][ns][3] - nm1) * L2E);
                    ps0 += p0 + p1; ps1 += p2 + p3;
                    sacc[ms][ns][0] = rn_tf32(p0);
                    sacc[ms][ns][1] = rn_tf32(p1);
                    sacc[ms][ns][2] = rn_tf32(p2);
                    sacc[ms][ns][3] = rn_tf32(p3);
                }
                ps0 += __shfl_xor_sync(0xffffffffu, ps0, 1);
                ps0 += __shfl_xor_sync(0xffffffffu, ps0, 2);
                ps1 += __shfl_xor_sync(0xffffffffu, ps1, 1);
                ps1 += __shfl_xor_sync(0xffffffffu, ps1, 2);
                li[ms][0] = li[ms][0] * f0 + ps0;
                li[ms][1] = li[ms][1] * f1 + ps1;
                #pragma unroll
                for (int ns = 0; ns < 8; ns++) {
                    accO[ms][ns][0] *= f0; accO[ms][ns][1] *= f0;
                    accO[ms][ns][2] *= f1; accO[ms][ns][3] *= f1;
                }
            }

            // ---- O += P V ; P A-frags via quad shuffles ----
            #pragma unroll
            for (int ks = 0; ks < 8; ks++) {
                const int kb = ks * 8;
                uint32_t a[2][4];
                #pragma unroll
                for (int ms = 0; ms < 2; ms++) {
                    float v0 = __shfl_sync(0xffffffffu, sacc[ms][ks][0], src_a);
                    float v1 = __shfl_sync(0xffffffffu, sacc[ms][ks][1], src_a);
                    a[ms][0] = fbits((tg & 1) ? v1 : v0);
                    float v2 = __shfl_sync(0xffffffffu, sacc[ms][ks][2], src_a);
                    float v3 = __shfl_sync(0xffffffffu, sacc[ms][ks][3], src_a);
                    a[ms][1] = fbits((tg & 1) ? v3 : v2);
                    float v4 = __shfl_sync(0xffffffffu, sacc[ms][ks][0], src_b);
                    float v5 = __shfl_sync(0xffffffffu, sacc[ms][ks][1], src_b);
                    a[ms][2] = fbits((tg & 1) ? v5 : v4);
                    float v6 = __shfl_sync(0xffffffffu, sacc[ms][ks][2], src_b);
                    float v7 = __shfl_sync(0xffffffffu, sacc[ms][ks][3], src_b);
                    a[ms][3] = fbits((tg & 1) ? v7 : v6);
                }
                #pragma unroll
                for (int ns = 0; ns < 8; ns++) {
                    uint32_t b[2];
                    b[0] = fbits(Vst[(kb + tg) * PVp + ns * 8 + gi]);
                    b[1] = fbits(Vst[(kb + tg + 4) * PVp + ns * 8 + gi]);
                    mma_tf32(accO[0][ns], a[0], b);
                    mma_tf32(accO[1][ns], a[1], b);
                }
            }
        }

        __syncthreads();
        if (kt + 2 <= kt_end) {
            const float* Kt = Kg + (size_t)(kt + 2) * AKT * 64;
            const float* Vt = Vg + (size_t)(kt + 2) * AKT * 64;
            const uint32_t sb = smb + (uint32_t)((kt & 1) * ASS) * 4;
            #pragma unroll
            for (int i = 0; i < 8; i++) {
                int r = ldr + i * 8;
                cp16(sb + (uint32_t)(r * PK + ldc) * 4,             Kt + r * 64 + ldc);
                cp16(sb + (uint32_t)(AKT * PK + r * PVp + ldc) * 4, Vt + r * 64 + ldc);
            }
        }
        CP_COMMIT();
    }

    // ---- write y (tf32-rounded for proj GEMM) ----
    const int b = bh >> 4, h = bh & (NH_ - 1);
    #pragma unroll
    for (int ms = 0; ms < 2; ms++) {
        float i0 = 1.f / li[ms][0], i1 = 1.f / li[ms][1];
        int q0 = qt * AQT + wm + ms * 16 + gi, q1 = q0 + 8;
        float* y0 = g_y + ((size_t)b * T_ + q0) * C_ + h * HS_;
        float* y1 = g_y + ((size_t)b * T_ + q1) * C_ + h * HS_;
        #pragma unroll
        for (int ns = 0; ns < 8; ns++) {
            int c0 = ns * 8 + tg * 2;
            *(float2*)(y0 + c0) = make_float2(rn_tf32(accO[ms][ns][0] * i0),
                                              rn_tf32(accO[ms][ns][1] * i0));
            *(float2*)(y1 + c0) = make_float2(rn_tf32(accO[ms][ns][2] * i1),
                                              rn_tf32(accO[ms][ns][3] * i1));
        }
    }
}

// ---------------------------------------------------------------------------
extern "C" void kernel_launch(void* const* d_in, const int* in_sizes, int n_in,
                              void* d_out, int out_size)
{
    (void)in_sizes; (void)n_in; (void)out_size;
    const float* x  = (const float*)d_in[0];
    const float* Wk = (const float*)d_in[1];
    const float* Wq = (const float*)d_in[2];
    const float* Wv = (const float*)d_in[3];
    const float* Wp = (const float*)d_in[4];
    float* out = (float*)d_out;

    static int attr_done = 0;
    if (!attr_done) {
        cudaFuncSetAttribute(attn_mma,     cudaFuncAttributeMaxDynamicSharedMemorySize, ASMEM);
        cudaFuncSetAttribute(gemm_qkv_tc,  cudaFuncAttributeMaxDynamicSharedMemorySize, GSMEM);
        cudaFuncSetAttribute(gemm_proj_tc, cudaFuncAttributeMaxDynamicSharedMemorySize, GSMEM);
        attr_done = 1;
    }

    round_x_kernel<<<2048, 256>>>(x);
    transpose_w_kernel<<<dim3(32, 32, 4), dim3(32, 8)>>>(Wq, Wk, Wv, Wp);

    gemm_qkv_tc<<<dim3(C_ / GBN, M_ / GBM, 3), 128, GSMEM>>>();

    attn_mma<<<dim3(T_ / AQT, B_ * NH_), 128, ASMEM>>>();

    gemm_proj_tc<<<dim3(C_ / GBN, M_ / GBM, 1), 128, GSMEM>>>(out);
}

// round 8
// speedup vs baseline: 1.7687x; 1.5132x over previous
#include <cuda_runtime.h>
#include <cuda_fp16.h>
#include <cstdint>

#define B_  4
#define T_  2048
#define C_  1024
#define NH_ 16
#define HS_ 64
#define M_  (B_*T_)   // 8192

// ---------------- scratch (static device arrays: allocation-free) ----------
__device__ __half g_q [(size_t)M_ * C_];   // [B,H,T,HS] fp16 (pre-scaled 1/8)
__device__ __half g_k [(size_t)M_ * C_];
__device__ __half g_v [(size_t)M_ * C_];
__device__ __half g_y [(size_t)M_ * C_];   // [B,T,C] fp16
__device__ __half g_xt[(size_t)M_ * C_];   // x -> fp16
__device__ __half g_wt[(size_t)4 * C_ * C_]; // (32*W)^T K-major fp16: q,k,v,p

// ---------------- helpers ---------------------------------------------------
__device__ __forceinline__ uint32_t smem_u32(const void* p) {
    uint32_t a;
    asm("{ .reg .u64 t; cvta.to.shared.u64 t, %1; cvt.u32.u64 %0, t; }" : "=r"(a) : "l"(p));
    return a;
}
__device__ __forceinline__ float ex2(float x) {
    float y; asm("ex2.approx.f32 %0, %1;" : "=f"(y) : "f"(x)); return y;
}
__device__ __forceinline__ uint32_t h2bits(__half2 h) { return *(uint32_t*)&h; }
__device__ __forceinline__ uint32_t packh2(float lo, float hi) {
    __half2 h = __floats2half2_rn(lo, hi);
    return *(uint32_t*)&h;
}
// D(fp32) += A(fp16 m16k16) * B(fp16 k16n8)
__device__ __forceinline__ void mma16(float* d, const uint32_t* a, uint32_t b0, uint32_t b1) {
    asm volatile("mma.sync.aligned.m16n8k16.row.col.f32.f16.f16.f32 "
                 "{%0,%1,%2,%3}, {%4,%5,%6,%7}, {%8,%9}, {%0,%1,%2,%3};"
                 : "+f"(d[0]), "+f"(d[1]), "+f"(d[2]), "+f"(d[3])
                 : "r"(a[0]), "r"(a[1]), "r"(a[2]), "r"(a[3]), "r"(b0), "r"(b1));
}
#define LDSM4(r0,r1,r2,r3,addr) \
    asm volatile("ldmatrix.sync.aligned.m8n8.x4.shared.b16 {%0,%1,%2,%3}, [%4];" \
                 : "=r"(r0),"=r"(r1),"=r"(r2),"=r"(r3) : "r"(addr))
#define LDSM4T(r0,r1,r2,r3,addr) \
    asm volatile("ldmatrix.sync.aligned.m8n8.x4.trans.shared.b16 {%0,%1,%2,%3}, [%4];" \
                 : "=r"(r0),"=r"(r1),"=r"(r2),"=r"(r3) : "r"(addr))
__device__ __forceinline__ void cp16(uint32_t dst, const void* src) {
    asm volatile("cp.async.cg.shared.global [%0], [%1], 16;" :: "r"(dst), "l"(src));
}
#define CP_COMMIT() asm volatile("cp.async.commit_group;" ::: "memory")
#define CP_WAIT1()  asm volatile("cp.async.wait_group 1;" ::: "memory")

// ---------------- prepass: x -> fp16 ---------------------------------------
__global__ __launch_bounds__(256) void cvt_x_kernel(const float* __restrict__ x) {
    size_t i0 = ((size_t)blockIdx.x * 256 + threadIdx.x) * 8;
    float4 a = *(const float4*)(x + i0);
    float4 b = *(const float4*)(x + i0 + 4);
    uint4 u;
    u.x = packh2(a.x, a.y); u.y = packh2(a.z, a.w);
    u.z = packh2(b.x, b.y); u.w = packh2(b.z, b.w);
    *(uint4*)(g_xt + i0) = u;
}

// ---------------- prepass: transpose + (x32) + fp16: g_wt[slot][n][k] ------
__global__ __launch_bounds__(256) void transpose_w_kernel(const float* __restrict__ Wq,
                                                          const float* __restrict__ Wk,
                                                          const float* __restrict__ Wv,
                                                          const float* __restrict__ Wp) {
    __shared__ float tile[32][33];
    const int z = blockIdx.z;
    const float* src = (z == 0) ? Wq : (z == 1) ? Wk : (z == 2) ? Wv : Wp;
    __half* dst = g_wt + ((size_t)z << 20);
    int x = blockIdx.x * 32 + threadIdx.x;   // n
    int y = blockIdx.y * 32 + threadIdx.y;   // k
    #pragma unroll
    for (int i = 0; i < 32; i += 8)
        tile[threadIdx.y + i][threadIdx.x] = src[(size_t)(y + i) * C_ + x];
    __syncthreads();
    int xo = blockIdx.y * 32 + threadIdx.x;  // k
    int yo = blockIdx.x * 32 + threadIdx.y;  // n
    #pragma unroll
    for (int i = 0; i < 32; i += 8)
        dst[(size_t)(yo + i) * C_ + xo] = __float2half_rn(32.0f * tile[threadIdx.x][threadIdx.y + i]);
}

// ---------------- fp16 mma GEMM: 128x128 block, 64x64 warp tile -------------
// out = A[M,K] * Wt[N,K]^T; k-chunk 16; 3-stage cp.async; 128 thr (2x2 warps)
#define GBM 128
#define GBN 128
#define GBK 16
#define GPH 24                       // smem pitch in halfs (16 + 8 pad)
#define NCH  (C_ / GBK)              // 64
#define GSSH (2 * 128 * GPH)         // halfs per stage (A+B) = 6144
#define GSMEM (3 * GSSH * 2)         // 36864 B

__device__ __forceinline__ void gemm_core(const __half* __restrict__ A,
                                          const __half* __restrict__ Bt,
                                          float* __restrict__ foutp,
                                          __half* __restrict__ houtp,
                                          float out_scale)
{
    extern __shared__ __align__(16) char gsmraw[];
    __half* gsm = (__half*)gsmraw;
    const uint32_t smb = smem_u32(gsmraw);

    const int tid = threadIdx.x, lane = tid & 31, wid = tid >> 5;
    const int wm = (wid >> 1) * 64;
    const int wn = (wid & 1) * 64;
    const int gi = lane >> 2, tg = lane & 3;

    const int brow = blockIdx.y * GBM, bcol = blockIdx.x * GBN;

    // loader: thread tid owns row tid of A and of B (2 cp16 each per chunk)
    const __half* Ag = A  + (size_t)(brow + tid) * C_;
    const __half* Bg = Bt + (size_t)(bcol + tid) * C_;
    const uint32_t sAr = smb + (uint32_t)(tid * GPH) * 2;
    const uint32_t sBr = sAr + (uint32_t)(128 * GPH) * 2;

    float acc[4][8][4];
    #pragma unroll
    for (int i = 0; i < 4; i++)
        #pragma unroll
        for (int j = 0; j < 8; j++)
            #pragma unroll
            for (int q = 0; q < 4; q++) acc[i][j][q] = 0.f;

    #pragma unroll
    for (int s = 0; s < 2; s++) {
        cp16(sAr + (uint32_t)(s * GSSH) * 2,      Ag + s * GBK);
        cp16(sAr + (uint32_t)(s * GSSH) * 2 + 16, Ag + s * GBK + 8);
        cp16(sBr + (uint32_t)(s * GSSH) * 2,      Bg + s * GBK);
        cp16(sBr + (uint32_t)(s * GSSH) * 2 + 16, Bg + s * GBK + 8);
        CP_COMMIT();
    }

    for (int c = 0; c < NCH; c++) {
        CP_WAIT1();
        __syncthreads();
        const __half* Ac = gsm + (c % 3) * GSSH;
        const __half* Bc = Ac + 128 * GPH;

        uint32_t af[4][4], bf[8][2];
        #pragma unroll
        for (int ms = 0; ms < 4; ms++) {
            int r = wm + ms * 16 + gi;
            af[ms][0] = *(const uint32_t*)&Ac[r * GPH + 2 * tg];
            af[ms][1] = *(const uint32_t*)&Ac[(r + 8) * GPH + 2 * tg];
            af[ms][2] = *(const uint32_t*)&Ac[r * GPH + 8 + 2 * tg];
            af[ms][3] = *(const uint32_t*)&Ac[(r + 8) * GPH + 8 + 2 * tg];
        }
        #pragma unroll
        for (int ns = 0; ns < 8; ns++) {
            int n = wn + ns * 8 + gi;
            bf[ns][0] = *(const uint32_t*)&Bc[n * GPH + 2 * tg];
            bf[ns][1] = *(const uint32_t*)&Bc[n * GPH + 8 + 2 * tg];
        }
        #pragma unroll
        for (int ms = 0; ms < 4; ms++)
            #pragma unroll
            for (int ns = 0; ns < 8; ns++)
                mma16(acc[ms][ns], af[ms], bf[ns][0], bf[ns][1]);

        __syncthreads();
        if (c + 2 < NCH) {
            const int s = (c + 2) % 3, k0 = (c + 2) * GBK;
            cp16(sAr + (uint32_t)(s * GSSH) * 2,      Ag + k0);
            cp16(sAr + (uint32_t)(s * GSSH) * 2 + 16, Ag + k0 + 8);
            cp16(sBr + (uint32_t)(s * GSSH) * 2,      Bg + k0);
            cp16(sBr + (uint32_t)(s * GSSH) * 2 + 16, Bg + k0 + 8);
        }
        CP_COMMIT();
    }

    #pragma unroll
    for (int ms = 0; ms < 4; ms++) {
        int r0 = brow + wm + ms * 16 + gi;
        int r1 = r0 + 8;
        #pragma unroll
        for (int ns = 0; ns < 8; ns++) {
            int n = bcol + wn + ns * 8 + tg * 2;
            if (houtp) {   // head layout [B,H,T,HS], fp16, scaled
                int h = n >> 6, d0 = n & 63;
                __half* p0 = houtp + (((size_t)(r0 >> 11) * NH_ + h) * T_ + (r0 & (T_-1))) * HS_ + d0;
                __half* p1 = houtp + (((size_t)(r1 >> 11) * NH_ + h) * T_ + (r1 & (T_-1))) * HS_ + d0;
                *(__half2*)p0 = __floats2half2_rn(acc[ms][ns][0] * out_scale, acc[ms][ns][1] * out_scale);
                *(__half2*)p1 = __floats2half2_rn(acc[ms][ns][2] * out_scale, acc[ms][ns][3] * out_scale);
            } else {       // fp32 [M,N]
                *(float2*)(foutp + (size_t)r0 * C_ + n) =
                    make_float2(acc[ms][ns][0] * out_scale, acc[ms][ns][1] * out_scale);
                *(float2*)(foutp + (size_t)r1 * C_ + n) =
                    make_float2(acc[ms][ns][2] * out_scale, acc[ms][ns][3] * out_scale);
            }
        }
    }
}

__global__ __launch_bounds__(128, 2) void gemm_qkv_tc() {
    const int z = blockIdx.z;
    const __half* Bt = g_wt + ((size_t)z << 20);
    __half* o = (z == 0) ? g_q : (z == 1) ? g_k : g_v;
    // W was pre-scaled by 32; Q additionally scaled by 1/sqrt(HS)=0.125
    float sc = (z == 0) ? (0.125f / 32.0f) : (1.0f / 32.0f);
    gemm_core(g_xt, Bt, nullptr, o, sc);
}
__global__ __launch_bounds__(128, 2) void gemm_proj_tc(float* __restrict__ out) {
    gemm_core(g_y, g_wt + ((size_t)3 << 20), out, nullptr, 1.0f / 32.0f);
}

// ---------------- flash attention: fp16 mma, ldmatrix, 2-stage cp.async -----
#define AQT 128
#define AKT 64
#define PH  72                         // smem pitch (halfs): 64 + 8
#define ASTGH (2 * AKT * PH)           // halfs per stage (K+V) = 9216
#define ASMEM (2 * ASTGH * 2)          // 36864 B
#define L2E 1.4426950408889634f

__global__ __launch_bounds__(128) void attn_mma()
{
    extern __shared__ __align__(16) char asmraw[];
    __half* smh = (__half*)asmraw;
    const uint32_t smb = smem_u32(asmraw);

    const int qt = blockIdx.x, bh = blockIdx.y;
    const int tid = threadIdx.x, wid = tid >> 5, lane = tid & 31;
    const int gi = lane >> 2, tg = lane & 3;
    const int wm = wid * 32;

    const __half* Qg = g_q + ((size_t)bh * T_ + (size_t)qt * AQT) * HS_;
    const __half* Kg = g_k + (size_t)bh * T_ * HS_;
    const __half* Vg = g_v + (size_t)bh * T_ * HS_;

    const int kt_end = 2 * qt + 1;

    // ldmatrix per-thread address components
    const int l7 = lane & 7;
    const int kColOff = 8 * ((lane >> 3) & 1);      // k lower/upper 8
    const int nRowOff = 8 * (lane >> 4);            // ns within pair

    // ---- prologue: stage0 <- tile 0 ----
    #pragma unroll
    for (int i = 0; i < 4; i++) {
        int id = tid + i * 128, r = id >> 3, c8 = (id & 7) * 8;
        cp16(smb + (uint32_t)(r * PH + c8) * 2,             Kg + r * 64 + c8);
        cp16(smb + (uint32_t)(AKT * PH + r * PH + c8) * 2,  Vg + r * 64 + c8);
    }
    CP_COMMIT();

    // ---- stage Q into stage-1 region; extract fp16 A-fragments ----
    __half* Qtmp = smh + ASTGH;
    #pragma unroll
    for (int i = 0; i < 8; i++) {
        int id = tid + i * 128, r = id >> 3, c8 = (id & 7) * 8;
        *(uint4*)&Qtmp[r * PH + c8] = *(const uint4*)(Qg + r * 64 + c8);
    }
    __syncthreads();
    uint32_t aq[4][2][4];
    #pragma unroll
    for (int ks = 0; ks < 4; ks++) {
        #pragma unroll
        for (int ms = 0; ms < 2; ms++) {
            int r = wm + ms * 16 + gi;
            aq[ks][ms][0] = *(const uint32_t*)&Qtmp[r * PH + 16 * ks + 2 * tg];
            aq[ks][ms][1] = *(const uint32_t*)&Qtmp[(r + 8) * PH + 16 * ks + 2 * tg];
            aq[ks][ms][2] = *(const uint32_t*)&Qtmp[r * PH + 16 * ks + 8 + 2 * tg];
            aq[ks][ms][3] = *(const uint32_t*)&Qtmp[(r + 8) * PH + 16 * ks + 8 + 2 * tg];
        }
    }
    __syncthreads();

    // ---- prologue: stage1 <- tile 1 ----
    {
        const __half* Kt = Kg + (size_t)AKT * 64;
        const __half* Vt = Vg + (size_t)AKT * 64;
        #pragma unroll
        for (int i = 0; i < 4; i++) {
            int id = tid + i * 128, r = id >> 3, c8 = (id & 7) * 8;
            cp16(smb + (uint32_t)(ASTGH + r * PH + c8) * 2,            Kt + r * 64 + c8);
            cp16(smb + (uint32_t)(ASTGH + AKT * PH + r * PH + c8) * 2, Vt + r * 64 + c8);
        }
        CP_COMMIT();
    }

    float accO[2][8][4];
    #pragma unroll
    for (int ms = 0; ms < 2; ms++)
        #pragma unroll
        for (int ns = 0; ns < 8; ns++)
            #pragma unroll
            for (int q = 0; q < 4; q++) accO[ms][ns][q] = 0.f;
    float mx[2][2] = {{-1e30f, -1e30f}, {-1e30f, -1e30f}};
    float li[2][2] = {{0.f, 0.f}, {0.f, 0.f}};

    for (int kt = 0; kt <= kt_end; kt++) {
        CP_WAIT1();
        __syncthreads();
        const uint32_t skb = smb + (uint32_t)((kt & 1) * ASTGH) * 2;            // K stage
        const uint32_t svb = skb + (uint32_t)(AKT * PH) * 2;                    // V stage

        if (kt * AKT <= qt * AQT + wm + 31) {   // warp not fully masked
            // ---- S = Q K^T ----
            float sacc[2][8][4];
            #pragma unroll
            for (int ms = 0; ms < 2; ms++)
                #pragma unroll
                for (int ns = 0; ns < 8; ns++)
                    #pragma unroll
                    for (int q = 0; q < 4; q++) sacc[ms][ns][q] = 0.f;

            #pragma unroll
            for (int ks = 0; ks < 4; ks++) {
                uint32_t bk[4][4];
                #pragma unroll
                for (int p = 0; p < 4; p++) {
                    uint32_t addr = skb + (uint32_t)((16 * p + nRowOff + l7) * PH
                                                     + 16 * ks + kColOff) * 2;
                    LDSM4(bk[p][0], bk[p][1], bk[p][2], bk[p][3], addr);
                }
                #pragma unroll
                for (int p = 0; p < 4; p++) {
                    mma16(sacc[0][2*p],   aq[ks][0], bk[p][0], bk[p][1]);
                    mma16(sacc[1][2*p],   aq[ks][1], bk[p][0], bk[p][1]);
                    mma16(sacc[0][2*p+1], aq[ks][0], bk[p][2], bk[p][3]);
                    mma16(sacc[1][2*p+1], aq[ks][1], bk[p][2], bk[p][3]);
                }
            }

            if (kt >= 2 * qt) {   // diagonal region: causal mask
                #pragma unroll
                for (int ms = 0; ms < 2; ms++) {
                    int r0 = qt * AQT + wm + ms * 16 + gi, r1 = r0 + 8;
                    #pragma unroll
                    for (int ns = 0; ns < 8; ns++) {
                        int c0 = kt * AKT + ns * 8 + tg * 2;
                        if (c0     > r0) sacc[ms][ns][0] = -1e30f;
                        if (c0 + 1 > r0) sacc[ms][ns][1] = -1e30f;
                        if (c0     > r1) sacc[ms][ns][2] = -1e30f;
                        if (c0 + 1 > r1) sacc[ms][ns][3] = -1e30f;
                    }
                }
            }

            // ---- online softmax; sacc overwritten with P (fp32) ----
            #pragma unroll
            for (int ms = 0; ms < 2; ms++) {
                float tm0 = -1e30f, tm1 = -1e30f;
                #pragma unroll
                for (int ns = 0; ns < 8; ns++) {
                    tm0 = fmaxf(tm0, fmaxf(sacc[ms][ns][0], sacc[ms][ns][1]));
                    tm1 = fmaxf(tm1, fmaxf(sacc[ms][ns][2], sacc[ms][ns][3]));
                }
                tm0 = fmaxf(tm0, __shfl_xor_sync(0xffffffffu, tm0, 1));
                tm0 = fmaxf(tm0, __shfl_xor_sync(0xffffffffu, tm0, 2));
                tm1 = fmaxf(tm1, __shfl_xor_sync(0xffffffffu, tm1, 1));
                tm1 = fmaxf(tm1, __shfl_xor_sync(0xffffffffu, tm1, 2));
                float nm0 = fmaxf(mx[ms][0], tm0), nm1 = fmaxf(mx[ms][1], tm1);
                float f0 = ex2((mx[ms][0] - nm0) * L2E);
                float f1 = ex2((mx[ms][1] - nm1) * L2E);
                mx[ms][0] = nm0; mx[ms][1] = nm1;

                float ps0 = 0.f, ps1 = 0.f;
                #pragma unroll
                for (int ns = 0; ns < 8; ns++) {
                    float p0 = ex2((sacc[ms][ns][0] - nm0) * L2E);
                    float p1 = ex2((sacc[ms][ns][1] - nm0) * L2E);
                    float p2 = ex2((sacc[ms][ns][2] - nm1) * L2E);
                    float p3 = ex2((sacc[ms][ns][3] - nm1) * L2E);
                    ps0 += p0 + p1; ps1 += p2 + p3;
                    sacc[ms][ns][0] = p0; sacc[ms][ns][1] = p1;
                    sacc[ms][ns][2] = p2; sacc[ms][ns][3] = p3;
                }
                ps0 += __shfl_xor_sync(0xffffffffu, ps0, 1);
                ps0 += __shfl_xor_sync(0xffffffffu, ps0, 2);
                ps1 += __shfl_xor_sync(0xffffffffu, ps1, 1);
                ps1 += __shfl_xor_sync(0xffffffffu, ps1, 2);
                li[ms][0] = li[ms][0] * f0 + ps0;
                li[ms][1] = li[ms][1] * f1 + ps1;
                #pragma unroll
                for (int ns = 0; ns < 8; ns++) {
                    accO[ms][ns][0] *= f0; accO[ms][ns][1] *= f0;
                    accO[ms][ns][2] *= f1; accO[ms][ns][3] *= f1;
                }
            }

            // ---- O += P V : C-layout -> fp16 A-layout via cvt (no shfl) ----
            #pragma unroll
            for (int kc = 0; kc < 4; kc++) {
                uint32_t bv[4][4];
                #pragma unroll
                for (int p = 0; p < 4; p++) {
                    uint32_t addr = svb + (uint32_t)((16 * kc + kColOff + l7) * PH
                                                     + 16 * p + nRowOff) * 2;
                    LDSM4T(bv[p][0], bv[p][1], bv[p][2], bv[p][3], addr);
                }
                uint32_t ap[2][4];
                #pragma unroll
                for (int ms = 0; ms < 2; ms++) {
                    ap[ms][0] = packh2(sacc[ms][2*kc][0],   sacc[ms][2*kc][1]);
                    ap[ms][1] = packh2(sacc[ms][2*kc][2],   sacc[ms][2*kc][3]);
                    ap[ms][2] = packh2(sacc[ms][2*kc+1][0], sacc[ms][2*kc+1][1]);
                    ap[ms][3] = packh2(sacc[ms][2*kc+1][2], sacc[ms][2*kc+1][3]);
                }
                #pragma unroll
                for (int p = 0; p < 4; p++) {
                    mma16(accO[0][2*p],   ap[0], bv[p][0], bv[p][1]);
                    mma16(accO[1][2*p],   ap[1], bv[p][0], bv[p][1]);
                    mma16(accO[0][2*p+1], ap[0], bv[p][2], bv[p][3]);
                    mma16(accO[1][2*p+1], ap[1], bv[p][2], bv[p][3]);
                }
            }
        }

        __syncthreads();
        if (kt + 2 <= kt_end) {
            const __half* Kt = Kg + (size_t)(kt + 2) * AKT * 64;
            const __half* Vt = Vg + (size_t)(kt + 2) * AKT * 64;
            const uint32_t sb = smb + (uint32_t)((kt & 1) * ASTGH) * 2;
            #pragma unroll
            for (int i = 0; i < 4; i++) {
                int id = tid + i * 128, r = id >> 3, c8 = (id & 7) * 8;
                cp16(sb + (uint32_t)(r * PH + c8) * 2,            Kt + r * 64 + c8);
                cp16(sb + (uint32_t)(AKT * PH + r * PH + c8) * 2, Vt + r * 64 + c8);
            }
        }
        CP_COMMIT();
    }

    // ---- write y (fp16 for proj GEMM) ----
    const int b = bh >> 4, h = bh & (NH_ - 1);
    #pragma unroll
    for (int ms = 0; ms < 2; ms++) {
        float i0 = 1.f / li[ms][0], i1 = 1.f / li[ms][1];
        int q0 = qt * AQT + wm + ms * 16 + gi, q1 = q0 + 8;
        __half* y0 = g_y + ((size_t)b * T_ + q0) * C_ + h * HS_;
        __half* y1 = g_y + ((size_t)b * T_ + q1) * C_ + h * HS_;
        #pragma unroll
        for (int ns = 0; ns < 8; ns++) {
            int c0 = ns * 8 + tg * 2;
            *(__half2*)(y0 + c0) = __floats2half2_rn(accO[ms][ns][0] * i0, accO[ms][ns][1] * i0);
            *(__half2*)(y1 + c0) = __floats2half2_rn(accO[ms][ns][2] * i1, accO[ms][ns][3] * i1);
        }
    }
}

// ---------------------------------------------------------------------------
extern "C" void kernel_launch(void* const* d_in, const int* in_sizes, int n_in,
                              void* d_out, int out_size)
{
    (void)in_sizes; (void)n_in; (void)out_size;
    const float* x  = (const float*)d_in[0];
    const float* Wk = (const float*)d_in[1];
    const float* Wq = (const float*)d_in[2];
    const float* Wv = (const float*)d_in[3];
    const float* Wp = (const float*)d_in[4];
    float* out = (float*)d_out;

    static int attr_done = 0;
    if (!attr_done) {
        cudaFuncSetAttribute(attn_mma,     cudaFuncAttributeMaxDynamicSharedMemorySize, ASMEM);
        cudaFuncSetAttribute(gemm_qkv_tc,  cudaFuncAttributeMaxDynamicSharedMemorySize, GSMEM);
        cudaFuncSetAttribute(gemm_proj_tc, cudaFuncAttributeMaxDynamicSharedMemorySize, GSMEM);
        attr_done = 1;
    }

    cvt_x_kernel<<<(M_ * C_) / (256 * 8), 256>>>(x);
    transpose_w_kernel<<<dim3(32, 32, 4), dim3(32, 8)>>>(Wq, Wk, Wv, Wp);

    gemm_qkv_tc<<<dim3(C_ / GBN, M_ / GBM, 3), 128, GSMEM>>>();

    attn_mma<<<dim3(T_ / AQT, B_ * NH_), 128, ASMEM>>>();

    gemm_proj_tc<<<dim3(C_ / GBN, M_ / GBM, 1), 128, GSMEM>>>(out);
}